// round 2
// baseline (speedup 1.0000x reference)
#include <cuda_runtime.h>
#include <math.h>

// Problem constants (fixed for this dataset instance)
#define B_    1024
#define H_    512
#define V_    2048
#define T_    32
#define G4H   2048          // 4*H
#define NTOT  4096          // 4H (gates) + V (logits) fused-GEMM width

// ---------------- persistent device state / scratch (no allocs allowed) ----
__device__ float g_h[B_ * H_];            // h_t            2 MB
__device__ float g_c[B_ * H_];            // c_t            2 MB
__device__ float g_gatepre[B_ * G4H];     // h_{t-1}@W_hh^T 8 MB
__device__ float g_Wc[NTOT * H_];         // [W_hh ; W_out] 8 MB
__device__ float g_WihT[V_ * G4H];        // W_ih^T        16 MB
__device__ int   g_p[B_];                 // argmax indices
__device__ float g_mask[B_];              // running mask

// ---------------------------------------------------------------- helpers
__device__ __forceinline__ float sigm(float x) {
    return 1.0f / (1.0f + expf(-x));
}

// ------------------------------------------------------------- init state
__global__ void init_kernel(const float* __restrict__ enc_h,
                            const float* __restrict__ enc_c) {
    int idx = blockIdx.x * blockDim.x + threadIdx.x;
    if (idx < B_ * H_) {
        g_h[idx] = enc_h[idx];
        g_c[idx] = enc_c[idx];
    }
    if (idx < B_) {
        g_mask[idx] = 1.0f;
        g_p[idx] = 0;
    }
}

// --------------------------------------------- build Wc = [W_hh ; W_out]
__global__ void build_wc_kernel(const float* __restrict__ W_hh,
                                const float* __restrict__ W_out) {
    int idx = blockIdx.x * blockDim.x + threadIdx.x;   // over NTOT*H_/4 float4s
    const int c4_per_row = H_ / 4;
    if (idx >= NTOT * c4_per_row) return;
    int row = idx / c4_per_row;
    int c4  = idx - row * c4_per_row;
    float4 v;
    if (row < G4H)
        v = *(const float4*)(W_hh + (size_t)row * H_ + c4 * 4);
    else
        v = *(const float4*)(W_out + (size_t)(row - G4H) * H_ + c4 * 4);
    *(float4*)(g_Wc + (size_t)row * H_ + c4 * 4) = v;
}

// ------------------------------------------------ transpose W_ih -> WihT
// W_ih: [4H, V] row-major.  g_WihT: [V, 4H] row-major (contiguous gather rows)
__global__ void transpose_kernel(const float* __restrict__ W) {
    __shared__ float tile[32][33];
    int x = blockIdx.x * 32 + threadIdx.x;
    int y = blockIdx.y * 32 + threadIdx.y;
#pragma unroll
    for (int j = 0; j < 32; j += 8)
        tile[threadIdx.y + j][threadIdx.x] = W[(size_t)(y + j) * V_ + x];
    __syncthreads();
    int x2 = blockIdx.y * 32 + threadIdx.x;
    int y2 = blockIdx.x * 32 + threadIdx.y;
#pragma unroll
    for (int j = 0; j < 32; j += 8)
        g_WihT[(size_t)(y2 + j) * G4H + x2] = tile[threadIdx.x][threadIdx.y + j];
}

// ------------------------------------------------------------- fused GEMM
// C[1024, 4096] = g_h[1024,512] @ g_Wc^T  (both K-major, "NT" layout)
// cols [0,2048)   -> g_gatepre (raw, biases added later in cell kernel)
// cols [2048,4096)-> logits + b_out   (written straight to d_out)
// 128x128 block tile, BK=16, 256 threads, 8x8 per-thread micro-tile,
// global->reg prefetch of next K-slab.
__global__ __launch_bounds__(256, 2)
void gemm_kernel(const float* __restrict__ bout,
                 float* __restrict__ logits) {
    __shared__ float As[16][128];
    __shared__ float Bs[16][128];

    const int tid = threadIdx.x;
    const int m0  = blockIdx.y * 128;
    const int n0  = blockIdx.x * 128;
    const bool isGate = (n0 < G4H);

    const float* Arow = g_h  + (size_t)m0 * H_;
    const float* Brow = g_Wc + (size_t)n0 * H_;

    const int lr = tid >> 2;        // 0..63
    const int lc = (tid & 3) * 4;   // 0,4,8,12

    // preload K-slab 0
    float4 a0r = *(const float4*)(Arow + (size_t)lr        * H_ + lc);
    float4 a1r = *(const float4*)(Arow + (size_t)(lr + 64) * H_ + lc);
    float4 b0r = *(const float4*)(Brow + (size_t)lr        * H_ + lc);
    float4 b1r = *(const float4*)(Brow + (size_t)(lr + 64) * H_ + lc);

    float acc[8][8];
#pragma unroll
    for (int i = 0; i < 8; i++)
#pragma unroll
        for (int j = 0; j < 8; j++) acc[i][j] = 0.0f;

    const int tRow = (tid >> 4) * 4;   // 0..60
    const int tCol = (tid & 15) * 4;   // 0..60

    const int KT = H_ / 16;            // 32 slabs
    for (int kt = 0; kt < KT; kt++) {
        // regs -> smem (transposed: [k][m])
        As[lc + 0][lr]      = a0r.x; As[lc + 1][lr]      = a0r.y;
        As[lc + 2][lr]      = a0r.z; As[lc + 3][lr]      = a0r.w;
        As[lc + 0][lr + 64] = a1r.x; As[lc + 1][lr + 64] = a1r.y;
        As[lc + 2][lr + 64] = a1r.z; As[lc + 3][lr + 64] = a1r.w;
        Bs[lc + 0][lr]      = b0r.x; Bs[lc + 1][lr]      = b0r.y;
        Bs[lc + 2][lr]      = b0r.z; Bs[lc + 3][lr]      = b0r.w;
        Bs[lc + 0][lr + 64] = b1r.x; Bs[lc + 1][lr + 64] = b1r.y;
        Bs[lc + 2][lr + 64] = b1r.z; Bs[lc + 3][lr + 64] = b1r.w;
        __syncthreads();

        if (kt + 1 < KT) {
            int k0 = (kt + 1) * 16;
            a0r = *(const float4*)(Arow + (size_t)lr        * H_ + k0 + lc);
            a1r = *(const float4*)(Arow + (size_t)(lr + 64) * H_ + k0 + lc);
            b0r = *(const float4*)(Brow + (size_t)lr        * H_ + k0 + lc);
            b1r = *(const float4*)(Brow + (size_t)(lr + 64) * H_ + k0 + lc);
        }

#pragma unroll
        for (int k = 0; k < 16; k++) {
            float4 av0 = *(const float4*)&As[k][tRow];
            float4 av1 = *(const float4*)&As[k][tRow + 64];
            float4 bv0 = *(const float4*)&Bs[k][tCol];
            float4 bv1 = *(const float4*)&Bs[k][tCol + 64];
            float a[8] = {av0.x, av0.y, av0.z, av0.w, av1.x, av1.y, av1.z, av1.w};
            float b[8] = {bv0.x, bv0.y, bv0.z, bv0.w, bv1.x, bv1.y, bv1.z, bv1.w};
#pragma unroll
            for (int i = 0; i < 8; i++)
#pragma unroll
                for (int j = 0; j < 8; j++)
                    acc[i][j] = fmaf(a[i], b[j], acc[i][j]);
        }
        __syncthreads();
    }

    // ---- epilogue: route to gatepre or logits(+bias)
#pragma unroll
    for (int ih = 0; ih < 2; ih++) {
#pragma unroll
        for (int i = 0; i < 4; i++) {
            int row = m0 + tRow + ih * 64 + i;
#pragma unroll
            for (int jh = 0; jh < 2; jh++) {
                int col = n0 + tCol + jh * 64;
                float4 v;
                v.x = acc[ih * 4 + i][jh * 4 + 0];
                v.y = acc[ih * 4 + i][jh * 4 + 1];
                v.z = acc[ih * 4 + i][jh * 4 + 2];
                v.w = acc[ih * 4 + i][jh * 4 + 3];
                if (isGate) {
                    *(float4*)(g_gatepre + (size_t)row * G4H + col) = v;
                } else {
                    int lcol = col - G4H;
                    float4 bb = *(const float4*)(bout + lcol);
                    v.x += bb.x; v.y += bb.y; v.z += bb.z; v.w += bb.w;
                    *(float4*)(logits + (size_t)row * V_ + lcol) = v;
                }
            }
        }
    }
}

// --------------------------------------------------------- LSTM cell step
// gates = g_gatepre + b_ih + b_hh + (use_x ? W_ih^T[p_b] : 0)
__global__ void cell_kernel(const float* __restrict__ b_ih,
                            const float* __restrict__ b_hh,
                            int use_x) {
    int idx = blockIdx.x * blockDim.x + threadIdx.x;
    if (idx >= B_ * H_) return;
    int b = idx >> 9;          // /H_
    int i = idx & (H_ - 1);

    const float* gp = g_gatepre + (size_t)b * G4H;
    float xi = 0.f, xf = 0.f, xg = 0.f, xo = 0.f;
    if (use_x) {
        const float* xr = g_WihT + (size_t)g_p[b] * G4H;
        xi = xr[i]; xf = xr[H_ + i]; xg = xr[2 * H_ + i]; xo = xr[3 * H_ + i];
    }
    float gi = gp[i]          + b_ih[i]          + b_hh[i]          + xi;
    float gf = gp[H_ + i]     + b_ih[H_ + i]     + b_hh[H_ + i]     + xf;
    float gg = gp[2 * H_ + i] + b_ih[2 * H_ + i] + b_hh[2 * H_ + i] + xg;
    float go = gp[3 * H_ + i] + b_ih[3 * H_ + i] + b_hh[3 * H_ + i] + xo;

    float cn = sigm(gf) * g_c[idx] + sigm(gi) * tanhf(gg);
    float hn = sigm(go) * tanhf(cn);
    g_c[idx] = cn;
    g_h[idx] = hn;
}

// ---------------------------------------------- argmax + outputs per step
// one block per batch row; first-index tie-break (matches jnp.argmax)
__global__ void argmax_kernel(const float* __restrict__ logits_t,
                              float* __restrict__ pred_t,
                              float* __restrict__ mask_t) {
    __shared__ float sv[256];
    __shared__ int   si[256];
    int b   = blockIdx.x;
    int tid = threadIdx.x;
    const float* row = logits_t + (size_t)b * V_;

    float bv = -INFINITY;
    int   bi = V_;
    for (int j = tid; j < V_; j += 256) {
        float v = row[j];
        if (v > bv || (v == bv && j < bi)) { bv = v; bi = j; }
    }
    sv[tid] = bv; si[tid] = bi;
    __syncthreads();
    for (int s = 128; s > 0; s >>= 1) {
        if (tid < s) {
            if (sv[tid + s] > sv[tid] ||
                (sv[tid + s] == sv[tid] && si[tid + s] < si[tid])) {
                sv[tid] = sv[tid + s];
                si[tid] = si[tid + s];
            }
        }
        __syncthreads();
    }
    if (tid == 0) {
        int p = si[0];
        g_p[b] = p;
        pred_t[(size_t)b * V_ + p] = 1.0f;      // region pre-zeroed
        mask_t[b] = g_mask[b];                  // record mask BEFORE update
        if (p == 0) g_mask[b] = 0.0f;           // eos_idx = 0
    }
}

// ---------------------------------------------------------------- driver
extern "C" void kernel_launch(void* const* d_in, const int* in_sizes, int n_in,
                              void* d_out, int out_size) {
    const float* enc_h = (const float*)d_in[0];
    const float* enc_c = (const float*)d_in[1];
    const float* W_ih  = (const float*)d_in[2];
    const float* W_hh  = (const float*)d_in[3];
    const float* b_ih  = (const float*)d_in[4];
    const float* b_hh  = (const float*)d_in[5];
    const float* W_out = (const float*)d_in[6];
    const float* b_out = (const float*)d_in[7];
    (void)in_sizes; (void)n_in; (void)out_size;

    float* out      = (float*)d_out;
    const size_t TBV = (size_t)T_ * B_ * V_;
    float* predicts = out;               // [T,B,V]
    float* logits   = out + TBV;         // [T,B,V]
    float* masks    = out + 2 * TBV;     // [T,1,B]

    // predicts region: one-hot -> zero it all once, scatter 1s later
    cudaMemsetAsync(predicts, 0, TBV * sizeof(float));

    init_kernel<<<(B_ * H_ + 255) / 256, 256>>>(enc_h, enc_c);
    build_wc_kernel<<<(NTOT * (H_ / 4) + 255) / 256, 256>>>(W_hh, W_out);
    transpose_kernel<<<dim3(V_ / 32, G4H / 32), dim3(32, 8)>>>(W_ih);

    // prologue GEMM: gatepre_0 = enc_h @ W_hh^T  (gate half of the grid only)
    gemm_kernel<<<dim3(16, 8), 256>>>(b_out, logits /*unused*/);

    for (int t = 0; t < T_; t++) {
        // h_t, c_t from gatepre + biases (+ one-hot gather for t>0)
        cell_kernel<<<(B_ * H_ + 255) / 256, 256>>>(b_ih, b_hh, t > 0 ? 1 : 0);
        // fused: gatepre_{t+1} = h_t@W_hh^T ; logits_t = h_t@W_out^T + b_out
        gemm_kernel<<<dim3(32, 8), 256>>>(b_out, logits + (size_t)t * B_ * V_);
        // argmax -> p_t, predicts_t scatter, masks_t, mask update
        argmax_kernel<<<B_, 256>>>(logits + (size_t)t * B_ * V_,
                                   predicts + (size_t)t * B_ * V_,
                                   masks + (size_t)t * B_);
    }
}